// round 2
// baseline (speedup 1.0000x reference)
#include <cuda_runtime.h>
#include <cuda_bf16.h>
#include <cstdint>

// ---------------------------------------------------------------------------
// Problem constants
// ---------------------------------------------------------------------------
#define BATCH 8192
#define INF   4096
#define OUTF  4096
#define EPS   1e-4f

// ---------------------------------------------------------------------------
// Scratch (device globals — no allocation allowed)
// ---------------------------------------------------------------------------
__device__ int8_t g_xbin[(size_t)BATCH * INF];   // 32 MB, {-1,0,1}
__device__ int8_t g_wbin[(size_t)OUTF * INF];    // 16 MB
__device__ float g_wscale[OUTF];
__device__ float g_mu[INF];
__device__ float g_rstd[INF];
__device__ float g_psum[32 * INF];
__device__ float g_psq[32 * INF];

// ---------------------------------------------------------------------------
// Kernel 1a: column partial sums (deterministic two-pass stats)
// ---------------------------------------------------------------------------
__global__ __launch_bounds__(256) void stats_partial_kernel(const float* __restrict__ x) {
    int c = blockIdx.x * 256 + threadIdx.x;
    int rc = blockIdx.y;
    float s = 0.f, q = 0.f;
    int r0 = rc * (BATCH / 32);
    for (int r = r0; r < r0 + (BATCH / 32); ++r) {
        float v = x[(size_t)r * INF + c];
        s += v;
        q += v * v;
    }
    g_psum[rc * INF + c] = s;
    g_psq[rc * INF + c] = q;
}

__global__ __launch_bounds__(256) void stats_finalize_kernel() {
    int c = blockIdx.x * 256 + threadIdx.x;
    float s = 0.f, q = 0.f;
    for (int rc = 0; rc < 32; ++rc) {
        s += g_psum[rc * INF + c];
        q += g_psq[rc * INF + c];
    }
    float mu = s * (1.0f / BATCH);
    float var = q * (1.0f / BATCH) - mu * mu;
    g_mu[c] = mu;
    g_rstd[c] = rsqrtf(var + EPS);
}

// ---------------------------------------------------------------------------
// Kernel 2: binarize activations -> int8 {-1,0,1}
// ---------------------------------------------------------------------------
__global__ __launch_bounds__(256) void binx_kernel(const float* __restrict__ x,
                                                   const float* __restrict__ gamma,
                                                   const float* __restrict__ beta) {
    size_t i4 = (size_t)blockIdx.x * 256 + threadIdx.x;   // float4 index
    float4 v = ((const float4*)x)[i4];
    int c = (int)((i4 & (INF / 4 - 1)) << 2);

    float xs[4] = {v.x, v.y, v.z, v.w};
    uint32_t packed = 0;
#pragma unroll
    for (int j = 0; j < 4; ++j) {
        float xn = (xs[j] - g_mu[c + j]) * g_rstd[c + j] * gamma[c + j] + beta[c + j];
        int sg = (xn > 0.f) - (xn < 0.f);
        packed |= ((uint32_t)(uint8_t)(int8_t)sg) << (8 * j);
    }
    ((uint32_t*)g_xbin)[i4] = packed;
}

// ---------------------------------------------------------------------------
// Kernel 3: binarize weights per row + L1 scale
// ---------------------------------------------------------------------------
__global__ __launch_bounds__(256) void binw_kernel(const float* __restrict__ w) {
    __shared__ float red[256];
    int row = blockIdx.x;
    int tid = threadIdx.x;
    const float* wr = w + (size_t)row * INF;

    float vals[16];
    float s = 0.f;
#pragma unroll
    for (int j = 0; j < 16; ++j) {
        vals[j] = wr[tid + j * 256];
        s += vals[j];
    }
    red[tid] = s;
    __syncthreads();
    for (int o = 128; o > 0; o >>= 1) {
        if (tid < o) red[tid] += red[tid + o];
        __syncthreads();
    }
    float mean = red[0] * (1.0f / INF);
    __syncthreads();

    float a = 0.f;
#pragma unroll
    for (int j = 0; j < 16; ++j) {
        float d = vals[j] - mean;
        float cl = fminf(fmaxf(d, -1.f), 1.f);
        a += fabsf(cl);
        int sg = (d > 0.f) - (d < 0.f);
        g_wbin[(size_t)row * INF + tid + j * 256] = (int8_t)sg;
    }
    red[tid] = a;
    __syncthreads();
    for (int o = 128; o > 0; o >>= 1) {
        if (tid < o) red[tid] += red[tid + o];
        __syncthreads();
    }
    if (tid == 0) g_wscale[row] = red[0] * (1.0f / INF);
}

// ---------------------------------------------------------------------------
// Kernel 4: int8 mma.sync GEMM
//   out[M,N] = relu(((float)(xbin @ wbin^T) + bias) * wscale)
//   CTA tile 128(M) x 256(N), 8 warps (warp tile 64x64), K-stage 64, 6 stages.
//   Smem rows: 64B straight copy of global k-run, 16B-XOR swizzle on (row&3).
//   Fragment reads: ld.shared.v2.b32 — same k-permutation applied to A cols
//   and B rows (dot product invariant), so no byte shuffling anywhere.
// ---------------------------------------------------------------------------
#define TM 128
#define TN 256
#define KS 64                    // K per stage (bytes/row)
#define NSTAGES 6
#define NKITER (INF / KS)        // 64
#define A_STAGE_BYTES (TM * KS)  // 8192
#define B_STAGE_BYTES (TN * KS)  // 16384
#define STAGE_BYTES (A_STAGE_BYTES + B_STAGE_BYTES)      // 24576
#define GEMM_SMEM (NSTAGES * STAGE_BYTES)                // 147456

__device__ __forceinline__ uint32_t smem_u32(const void* p) {
    uint32_t a;
    asm("{ .reg .u64 t; cvta.to.shared.u64 t, %1; cvt.u32.u64 %0, t; }"
        : "=r"(a) : "l"(p));
    return a;
}

__device__ __forceinline__ void cp_async16(uint32_t dst, const void* src) {
    asm volatile("cp.async.cg.shared.global [%0], [%1], 16;"
                 :: "r"(dst), "l"(src) : "memory");
}
__device__ __forceinline__ void cp_commit() {
    asm volatile("cp.async.commit_group;" ::: "memory");
}
template <int N>
__device__ __forceinline__ void cp_wait() {
    asm volatile("cp.async.wait_group %0;" :: "n"(N) : "memory");
}

__device__ __forceinline__ void lds64(uint32_t& lo, uint32_t& hi, uint32_t addr) {
    asm volatile("ld.shared.v2.b32 {%0, %1}, [%2];" : "=r"(lo), "=r"(hi) : "r"(addr));
}

__device__ __forceinline__ void imma16832(int* d, uint32_t a0, uint32_t a1,
                                          uint32_t a2, uint32_t a3,
                                          uint32_t b0, uint32_t b1) {
    asm volatile(
        "mma.sync.aligned.m16n8k32.row.col.s32.s8.s8.s32 "
        "{%0,%1,%2,%3}, {%4,%5,%6,%7}, {%8,%9}, {%0,%1,%2,%3};"
        : "+r"(d[0]), "+r"(d[1]), "+r"(d[2]), "+r"(d[3])
        : "r"(a0), "r"(a1), "r"(a2), "r"(a3), "r"(b0), "r"(b1));
}

// swizzled byte offset within a stage for (row, byte-in-row)
__device__ __forceinline__ uint32_t swz(int row, uint32_t b) {
    return (uint32_t)row * KS + (b ^ (((uint32_t)row & 3u) << 4));
}

__global__ __launch_bounds__(256, 1) void gemm_kernel(const float* __restrict__ bias,
                                                      float* __restrict__ out) {
    extern __shared__ char smem_raw[];
    const uint32_t sbase = smem_u32(smem_raw);

    const int tid = threadIdx.x;
    const int wid = tid >> 5;
    const int lane = tid & 31;
    const int lq = lane >> 2;       // 0..7  (row/col within fragment)
    const int lr = lane & 3;        // 0..3  (k group)
    const int tile_n = blockIdx.x;  // 0..15
    const int tile_m = blockIdx.y;  // 0..63
    const int wm = wid >> 2;        // 0..1
    const int wn = wid & 3;         // 0..3

    // producer mapping
    const int a_row = tid >> 1;                 // 0..127
    const int a_cb  = (tid & 1) * 32;           // byte 0 or 32
    const int b_row = tid;                      // 0..255

    const int8_t* Ag = g_xbin + ((size_t)tile_m * TM + a_row) * INF + a_cb;
    const int8_t* Bg = g_wbin + ((size_t)tile_n * TN + b_row) * INF;

    const uint32_t a_s0 = swz(a_row, (uint32_t)a_cb);
    const uint32_t a_s1 = swz(a_row, (uint32_t)a_cb + 16);
    const uint32_t b_s0 = swz(b_row, 0);
    const uint32_t b_s1 = swz(b_row, 16);
    const uint32_t b_s2 = swz(b_row, 32);
    const uint32_t b_s3 = swz(b_row, 48);

    // ---- prologue: fill NSTAGES-1 stages -------------------------------
#pragma unroll
    for (int s = 0; s < NSTAGES - 1; ++s) {
        uint32_t ab = sbase + s * STAGE_BYTES;
        uint32_t bb = ab + A_STAGE_BYTES;
        const int8_t* ag = Ag + s * KS;
        const int8_t* bg = Bg + s * KS;
        cp_async16(ab + a_s0, ag);
        cp_async16(ab + a_s1, ag + 16);
        cp_async16(bb + b_s0, bg);
        cp_async16(bb + b_s1, bg + 16);
        cp_async16(bb + b_s2, bg + 32);
        cp_async16(bb + b_s3, bg + 48);
        cp_commit();
    }

    int acc[4][8][4];
#pragma unroll
    for (int i = 0; i < 4; ++i)
#pragma unroll
        for (int j = 0; j < 8; ++j)
#pragma unroll
            for (int k = 0; k < 4; ++k) acc[i][j][k] = 0;

    // fragment smem bases (per-thread invariants)
    // A rows: wm*64 + mt*16 + lq (and +8);  B rows: wn*64 + nt*8 + lq
    const uint32_t frag_b = 8u * (uint32_t)lr;

    // ---- main loop ------------------------------------------------------
    for (int ks = 0; ks < NKITER; ++ks) {
        cp_wait<NSTAGES - 2>();
        __syncthreads();

        // prefetch stage ks + NSTAGES-1
        {
            int ps = ks + NSTAGES - 1;
            if (ps < NKITER) {
                int buf = ps % NSTAGES;
                uint32_t ab = sbase + buf * STAGE_BYTES;
                uint32_t bb = ab + A_STAGE_BYTES;
                const int8_t* ag = Ag + ps * KS;
                const int8_t* bg = Bg + ps * KS;
                cp_async16(ab + a_s0, ag);
                cp_async16(ab + a_s1, ag + 16);
                cp_async16(bb + b_s0, bg);
                cp_async16(bb + b_s1, bg + 16);
                cp_async16(bb + b_s2, bg + 32);
                cp_async16(bb + b_s3, bg + 48);
            }
            cp_commit();   // always commit (possibly empty) to keep counts aligned
        }

        const int buf = ks % NSTAGES;
        const uint32_t ab = sbase + buf * STAGE_BYTES;
        const uint32_t bb = ab + A_STAGE_BYTES;

#pragma unroll
        for (int s = 0; s < 2; ++s) {          // two k32 steps per stage
            const uint32_t kb = 32u * s + frag_b;
            uint32_t a0[4], a1[4], a2[4], a3[4];
#pragma unroll
            for (int mt = 0; mt < 4; ++mt) {
                int r0 = wm * 64 + mt * 16 + lq;
                lds64(a0[mt], a2[mt], ab + swz(r0, kb));
                lds64(a1[mt], a3[mt], ab + swz(r0 + 8, kb));
            }
            uint32_t b0[8], b1[8];
#pragma unroll
            for (int nt = 0; nt < 8; ++nt) {
                int n = wn * 64 + nt * 8 + lq;
                lds64(b0[nt], b1[nt], bb + swz(n, kb));
            }
#pragma unroll
            for (int mt = 0; mt < 4; ++mt)
#pragma unroll
                for (int nt = 0; nt < 8; ++nt)
                    imma16832(acc[mt][nt], a0[mt], a1[mt], a2[mt], a3[mt],
                              b0[nt], b1[nt]);
        }
    }

    // ---- epilogue -------------------------------------------------------
    const int n_base = tile_n * TN + wn * 64 + 2 * lr;
    const int m_base = tile_m * TM + wm * 64 + lq;
#pragma unroll
    for (int nt = 0; nt < 8; ++nt) {
        int n = n_base + nt * 8;
        float2 bb2 = *(const float2*)(bias + n);
        float2 sc2 = *(const float2*)(g_wscale + n);
#pragma unroll
        for (int mt = 0; mt < 4; ++mt) {
            int r = m_base + mt * 16;
            float2 v0, v1;
            v0.x = fmaxf(((float)acc[mt][nt][0] + bb2.x) * sc2.x, 0.f);
            v0.y = fmaxf(((float)acc[mt][nt][1] + bb2.y) * sc2.y, 0.f);
            v1.x = fmaxf(((float)acc[mt][nt][2] + bb2.x) * sc2.x, 0.f);
            v1.y = fmaxf(((float)acc[mt][nt][3] + bb2.y) * sc2.y, 0.f);
            *(float2*)(out + (size_t)r * OUTF + n) = v0;
            *(float2*)(out + (size_t)(r + 8) * OUTF + n) = v1;
        }
    }
}

// ---------------------------------------------------------------------------
// Launcher
// ---------------------------------------------------------------------------
extern "C" void kernel_launch(void* const* d_in, const int* in_sizes, int n_in,
                              void* d_out, int out_size) {
    (void)in_sizes; (void)n_in; (void)out_size;
    const float* x     = (const float*)d_in[0];
    const float* gamma = (const float*)d_in[1];
    const float* beta  = (const float*)d_in[2];
    const float* w     = (const float*)d_in[3];
    const float* bias  = (const float*)d_in[4];
    float* out = (float*)d_out;

    stats_partial_kernel<<<dim3(16, 32), 256>>>(x);
    stats_finalize_kernel<<<16, 256>>>();
    binx_kernel<<<(BATCH * INF / 4) / 256, 256>>>(x, gamma, beta);
    binw_kernel<<<OUTF, 256>>>(w);

    cudaFuncSetAttribute(gemm_kernel, cudaFuncAttributeMaxDynamicSharedMemorySize, GEMM_SMEM);
    gemm_kernel<<<dim3(OUTF / TN, BATCH / TM), 256, GEMM_SMEM>>>(bias, out);
}

// round 3
// speedup vs baseline: 2.0005x; 2.0005x over previous
#include <cuda_runtime.h>
#include <cstdint>

// ---------------------------------------------------------------------------
// Problem constants
// ---------------------------------------------------------------------------
#define BATCH 8192
#define INF   4096
#define OUTF  4096
#define EPS   1e-4f
#define KW    (INF / 32)          // 128 words per row

// ---------------------------------------------------------------------------
// Scratch (device globals — no allocation allowed)
// ---------------------------------------------------------------------------
__device__ uint32_t g_xb[(size_t)BATCH * KW];   // 4 MB packed sign bits
__device__ uint32_t g_wb[(size_t)OUTF * KW];    // 2 MB
__device__ float g_wscale[OUTF];
__device__ float g_thr[INF];
__device__ uint32_t g_flip[INF];
__device__ float g_psum[32 * INF];
__device__ float g_psq[32 * INF];

// ---------------------------------------------------------------------------
// helpers
// ---------------------------------------------------------------------------
__device__ __forceinline__ uint32_t smem_u32(const void* p) {
    uint32_t a;
    asm("{ .reg .u64 t; cvta.to.shared.u64 t, %1; cvt.u32.u64 %0, t; }"
        : "=r"(a) : "l"(p));
    return a;
}
__device__ __forceinline__ void cp_async16(uint32_t dst, const void* src) {
    asm volatile("cp.async.cg.shared.global [%0], [%1], 16;"
                 :: "r"(dst), "l"(src) : "memory");
}
__device__ __forceinline__ void cp_commit() {
    asm volatile("cp.async.commit_group;" ::: "memory");
}
template <int N>
__device__ __forceinline__ void cp_wait() {
    asm volatile("cp.async.wait_group %0;" :: "n"(N) : "memory");
}
__device__ __forceinline__ uint4 lds128(uint32_t addr) {
    uint4 v;
    asm volatile("ld.shared.v4.b32 {%0, %1, %2, %3}, [%4];"
                 : "=r"(v.x), "=r"(v.y), "=r"(v.z), "=r"(v.w) : "r"(addr));
    return v;
}

// ---------------------------------------------------------------------------
// Kernel 1a: column partial sums (deterministic two-pass stats)
// ---------------------------------------------------------------------------
__global__ __launch_bounds__(256) void stats_partial_kernel(const float* __restrict__ x) {
    int c = blockIdx.x * 256 + threadIdx.x;
    int rc = blockIdx.y;
    float s = 0.f, q = 0.f;
    int r0 = rc * (BATCH / 32);
    for (int r = r0; r < r0 + (BATCH / 32); ++r) {
        float v = x[(size_t)r * INF + c];
        s += v;
        q += v * v;
    }
    g_psum[rc * INF + c] = s;
    g_psq[rc * INF + c] = q;
}

// Kernel 1b: finalize -> per-column threshold + flip
// sign((x-mu)*rstd*gamma + beta):  s = gamma*rstd
//   s>0: bit = x > (mu - beta/s)          flip=0
//   s<0: bit = x < t  -> !(x>t)           flip=1
//   s=0: constant sign(beta)              t = -inf/+inf, flip=0
__global__ __launch_bounds__(256) void stats_finalize_kernel(const float* __restrict__ gamma,
                                                             const float* __restrict__ beta) {
    int c = blockIdx.x * 256 + threadIdx.x;
    float s = 0.f, q = 0.f;
    for (int rc = 0; rc < 32; ++rc) {
        s += g_psum[rc * INF + c];
        q += g_psq[rc * INF + c];
    }
    float mu = s * (1.0f / BATCH);
    float var = q * (1.0f / BATCH) - mu * mu;
    float rstd = rsqrtf(var + EPS);
    float sc = gamma[c] * rstd;
    float t;
    uint32_t fl;
    if (sc > 0.f) { t = mu - beta[c] / sc; fl = 0u; }
    else if (sc < 0.f) { t = mu - beta[c] / sc; fl = 1u; }
    else {
        t = (beta[c] > 0.f) ? __int_as_float(0xff800000)   // -inf -> always 1
                            : __int_as_float(0x7f800000);  // +inf -> always 0
        fl = 0u;
    }
    g_thr[c] = t;
    g_flip[c] = fl;
}

// ---------------------------------------------------------------------------
// Kernel 2: pack activation sign bits via ballot.
// grid (8192, 4) x 256.  Warp covers 128 cols: lane l takes cols c0+l+32j.
// ---------------------------------------------------------------------------
__global__ __launch_bounds__(256) void binx_pack(const float* __restrict__ x) {
    int row = blockIdx.x;
    int warp = threadIdx.x >> 5;
    int lane = threadIdx.x & 31;
    int c0 = (blockIdx.y * 8 + warp) * 128;
    const float* xr = x + (size_t)row * INF + c0 + lane;
    uint32_t* ow = g_xb + (size_t)row * KW + (blockIdx.y * 8 + warp) * 4;
#pragma unroll
    for (int j = 0; j < 4; ++j) {
        int c = c0 + lane + 32 * j;
        float v = xr[32 * j];
        uint32_t bit = ((v > g_thr[c]) ? 1u : 0u) ^ g_flip[c];
        uint32_t word = __ballot_sync(0xffffffffu, bit);
        if (lane == 0) ow[j] = word;
    }
}

// ---------------------------------------------------------------------------
// Kernel 3: pack weight sign bits (row-centered) + per-row L1 scale.
// One block (256 thr) per row. Lane l, iter j -> col = warp*512 + l + 32j.
// ---------------------------------------------------------------------------
__global__ __launch_bounds__(256) void binw_pack(const float* __restrict__ w) {
    __shared__ float red[256];
    int row = blockIdx.x;
    int tid = threadIdx.x;
    int warp = tid >> 5;
    int lane = tid & 31;
    const float* wr = w + (size_t)row * INF;

    float vals[16];
    float s = 0.f;
#pragma unroll
    for (int j = 0; j < 16; ++j) {
        vals[j] = wr[warp * 512 + lane + 32 * j];
        s += vals[j];
    }
    red[tid] = s;
    __syncthreads();
    for (int o = 128; o > 0; o >>= 1) {
        if (tid < o) red[tid] += red[tid + o];
        __syncthreads();
    }
    float mean = red[0] * (1.0f / INF);
    __syncthreads();

    float a = 0.f;
#pragma unroll
    for (int j = 0; j < 16; ++j) {
        float d = vals[j] - mean;
        a += fabsf(fminf(fmaxf(d, -1.f), 1.f));
        uint32_t word = __ballot_sync(0xffffffffu, d > 0.f);
        if (lane == 0) g_wb[(size_t)row * KW + warp * 16 + j] = word;
    }
    red[tid] = a;
    __syncthreads();
    for (int o = 128; o > 0; o >>= 1) {
        if (tid < o) red[tid] += red[tid + o];
        __syncthreads();
    }
    if (tid == 0) g_wscale[row] = red[0] * (1.0f / INF);
}

// ---------------------------------------------------------------------------
// Kernel 4: XNOR-popcount GEMM.
//   out[m,n] = relu(((4096 - 2*popc_sum) + bias[n]) * wscale[n])
//   CTA 128x128, 8 warps (warp 64Mx32N), thread 8x8 (m = +8i, n = +4j).
//   K chunks of 32 words, 3-stage cp.async ring, pitch 144B (conflict-free).
// ---------------------------------------------------------------------------
#define KC 32
#define PITCH 144
#define ASTG (128 * PITCH)                 // 18432
#define STG_BYTES (2 * ASTG)               // 36864
#define NST 3
#define NCHUNK (KW / KC)                   // 4
#define GEMM_SMEM (NST * STG_BYTES)        // 110592

__global__ __launch_bounds__(256, 1) void gemm_kernel(const float* __restrict__ bias,
                                                      float* __restrict__ out) {
    extern __shared__ char smem_raw[];
    const uint32_t sbase = smem_u32(smem_raw);

    const int tid = threadIdx.x;
    const int wid = tid >> 5;
    const int lane = tid & 31;
    const int wm = wid >> 2;        // 0..1
    const int wn = wid & 3;         // 0..3
    const int tm = lane >> 2;       // 0..7
    const int tn = lane & 3;        // 0..3
    const int tile_n = blockIdx.x;  // 0..31
    const int tile_m = blockIdx.y;  // 0..63

    // producer: thread -> one tile row (A for tid<128, B for tid>=128), 8x16B
    const int prow = tid & 127;
    const int isB = tid >> 7;
    const uint32_t* gsrc = isB ? (g_wb + ((size_t)tile_n * 128 + prow) * KW)
                               : (g_xb + ((size_t)tile_m * 128 + prow) * KW);
    const uint32_t sdst = (uint32_t)isB * ASTG + (uint32_t)prow * PITCH;

    // prologue: fill stages 0..NST-2
#pragma unroll
    for (int s = 0; s < NST - 1; ++s) {
        uint32_t sb = sbase + s * STG_BYTES + sdst;
        const uint32_t* g = gsrc + s * KC;
#pragma unroll
        for (int c = 0; c < 8; ++c) cp_async16(sb + c * 16, g + c * 4);
        cp_commit();
    }

    int acc[8][8];
#pragma unroll
    for (int i = 0; i < 8; ++i)
#pragma unroll
        for (int j = 0; j < 8; ++j) acc[i][j] = 0;

    const uint32_t aoff = (uint32_t)(wm * 64 + tm) * PITCH;
    const uint32_t boff = ASTG + (uint32_t)(wn * 32 + tn) * PITCH;

    for (int kc = 0; kc < NCHUNK; ++kc) {
        cp_wait<NST - 2>();
        __syncthreads();

        int ps = kc + NST - 1;
        if (ps < NCHUNK) {
            uint32_t sb = sbase + (ps % NST) * STG_BYTES + sdst;
            const uint32_t* g = gsrc + ps * KC;
#pragma unroll
            for (int c = 0; c < 8; ++c) cp_async16(sb + c * 16, g + c * 4);
        }
        cp_commit();

        const uint32_t stg = sbase + (kc % NST) * STG_BYTES;
#pragma unroll 1
        for (int k4 = 0; k4 < KC / 4; ++k4) {
            uint4 a[8], b[8];
#pragma unroll
            for (int i = 0; i < 8; ++i)
                a[i] = lds128(stg + aoff + (uint32_t)(i * 8) * PITCH + k4 * 16);
#pragma unroll
            for (int j = 0; j < 8; ++j)
                b[j] = lds128(stg + boff + (uint32_t)(j * 4) * PITCH + k4 * 16);
#pragma unroll
            for (int i = 0; i < 8; ++i)
#pragma unroll
                for (int j = 0; j < 8; ++j) {
                    acc[i][j] += __popc(a[i].x ^ b[j].x) + __popc(a[i].y ^ b[j].y) +
                                 __popc(a[i].z ^ b[j].z) + __popc(a[i].w ^ b[j].w);
                }
        }
    }

    // epilogue
    const int mb = tile_m * 128 + wm * 64 + tm;
    const int nb = tile_n * 128 + wn * 32 + tn;
#pragma unroll
    for (int j = 0; j < 8; ++j) {
        int n = nb + 4 * j;
        float bv = bias[n];
        float sv = g_wscale[n];
#pragma unroll
        for (int i = 0; i < 8; ++i) {
            int m = mb + 8 * i;
            float v = (float)(INF - 2 * acc[i][j]);
            out[(size_t)m * OUTF + n] = fmaxf((v + bv) * sv, 0.f);
        }
    }
}

// ---------------------------------------------------------------------------
// Launcher
// ---------------------------------------------------------------------------
extern "C" void kernel_launch(void* const* d_in, const int* in_sizes, int n_in,
                              void* d_out, int out_size) {
    (void)in_sizes; (void)n_in; (void)out_size;
    const float* x     = (const float*)d_in[0];
    const float* gamma = (const float*)d_in[1];
    const float* beta  = (const float*)d_in[2];
    const float* w     = (const float*)d_in[3];
    const float* bias  = (const float*)d_in[4];
    float* out = (float*)d_out;

    stats_partial_kernel<<<dim3(16, 32), 256>>>(x);
    stats_finalize_kernel<<<16, 256>>>(gamma, beta);
    binx_pack<<<dim3(BATCH, 4), 256>>>(x);
    binw_pack<<<OUTF, 256>>>(w);

    cudaFuncSetAttribute(gemm_kernel, cudaFuncAttributeMaxDynamicSharedMemorySize, GEMM_SMEM);
    gemm_kernel<<<dim3(OUTF / 128, BATCH / 128), 256, GEMM_SMEM>>>(bias, out);
}

// round 4
// speedup vs baseline: 2.0249x; 1.0122x over previous
#include <cuda_runtime.h>
#include <cstdint>

// ---------------------------------------------------------------------------
// Problem constants
// ---------------------------------------------------------------------------
#define BATCH 8192
#define INF   4096
#define OUTF  4096
#define EPS   1e-4f
#define KW    (INF / 32)          // 128 words per row

// ---------------------------------------------------------------------------
// Scratch (device globals — no allocation allowed)
// ---------------------------------------------------------------------------
__device__ uint32_t g_xb[(size_t)BATCH * KW];   // 4 MB packed sign bits
__device__ uint32_t g_wb[(size_t)OUTF * KW];    // 2 MB
__device__ float g_wscale[OUTF];
__device__ float g_thr[INF];
__device__ uint32_t g_flip[INF];
__device__ float g_psum[32 * INF];
__device__ float g_psq[32 * INF];

// ---------------------------------------------------------------------------
// helpers
// ---------------------------------------------------------------------------
__device__ __forceinline__ uint32_t smem_u32(const void* p) {
    uint32_t a;
    asm("{ .reg .u64 t; cvta.to.shared.u64 t, %1; cvt.u32.u64 %0, t; }"
        : "=r"(a) : "l"(p));
    return a;
}
__device__ __forceinline__ void cp_async16(uint32_t dst, const void* src) {
    asm volatile("cp.async.cg.shared.global [%0], [%1], 16;"
                 :: "r"(dst), "l"(src) : "memory");
}
__device__ __forceinline__ void cp_commit() {
    asm volatile("cp.async.commit_group;" ::: "memory");
}
template <int N>
__device__ __forceinline__ void cp_wait() {
    asm volatile("cp.async.wait_group %0;" :: "n"(N) : "memory");
}
__device__ __forceinline__ uint4 lds128(uint32_t addr) {
    uint4 v;
    asm volatile("ld.shared.v4.b32 {%0, %1, %2, %3}, [%4];"
                 : "=r"(v.x), "=r"(v.y), "=r"(v.z), "=r"(v.w) : "r"(addr));
    return v;
}

// ---------------------------------------------------------------------------
// Kernel 1a: column partial sums (deterministic two-pass stats)
// ---------------------------------------------------------------------------
__global__ __launch_bounds__(256) void stats_partial_kernel(const float* __restrict__ x) {
    int c = blockIdx.x * 256 + threadIdx.x;
    int rc = blockIdx.y;
    float s = 0.f, q = 0.f;
    int r0 = rc * (BATCH / 32);
    for (int r = r0; r < r0 + (BATCH / 32); ++r) {
        float v = x[(size_t)r * INF + c];
        s += v;
        q += v * v;
    }
    g_psum[rc * INF + c] = s;
    g_psq[rc * INF + c] = q;
}

// Kernel 1b: finalize -> per-column threshold + flip
__global__ __launch_bounds__(256) void stats_finalize_kernel(const float* __restrict__ gamma,
                                                             const float* __restrict__ beta) {
    int c = blockIdx.x * 256 + threadIdx.x;
    float s = 0.f, q = 0.f;
    for (int rc = 0; rc < 32; ++rc) {
        s += g_psum[rc * INF + c];
        q += g_psq[rc * INF + c];
    }
    float mu = s * (1.0f / BATCH);
    float var = q * (1.0f / BATCH) - mu * mu;
    float rstd = rsqrtf(var + EPS);
    float sc = gamma[c] * rstd;
    float t;
    uint32_t fl;
    if (sc > 0.f) { t = mu - beta[c] / sc; fl = 0u; }
    else if (sc < 0.f) { t = mu - beta[c] / sc; fl = 1u; }
    else {
        t = (beta[c] > 0.f) ? __int_as_float(0xff800000)   // -inf -> always 1
                            : __int_as_float(0x7f800000);  // +inf -> always 0
        fl = 0u;
    }
    g_thr[c] = t;
    g_flip[c] = fl;
}

// ---------------------------------------------------------------------------
// Kernel 2: pack activation sign bits via ballot.
// ---------------------------------------------------------------------------
__global__ __launch_bounds__(256) void binx_pack(const float* __restrict__ x) {
    int row = blockIdx.x;
    int warp = threadIdx.x >> 5;
    int lane = threadIdx.x & 31;
    int c0 = (blockIdx.y * 8 + warp) * 128;
    const float* xr = x + (size_t)row * INF + c0 + lane;
    uint32_t* ow = g_xb + (size_t)row * KW + (blockIdx.y * 8 + warp) * 4;
#pragma unroll
    for (int j = 0; j < 4; ++j) {
        int c = c0 + lane + 32 * j;
        float v = xr[32 * j];
        uint32_t bit = ((v > g_thr[c]) ? 1u : 0u) ^ g_flip[c];
        uint32_t word = __ballot_sync(0xffffffffu, bit);
        if (lane == 0) ow[j] = word;
    }
}

// ---------------------------------------------------------------------------
// Kernel 3: pack weight sign bits (row-centered) + per-row L1 scale.
// ---------------------------------------------------------------------------
__global__ __launch_bounds__(256) void binw_pack(const float* __restrict__ w) {
    __shared__ float red[256];
    int row = blockIdx.x;
    int tid = threadIdx.x;
    int warp = tid >> 5;
    int lane = tid & 31;
    const float* wr = w + (size_t)row * INF;

    float vals[16];
    float s = 0.f;
#pragma unroll
    for (int j = 0; j < 16; ++j) {
        vals[j] = wr[warp * 512 + lane + 32 * j];
        s += vals[j];
    }
    red[tid] = s;
    __syncthreads();
    for (int o = 128; o > 0; o >>= 1) {
        if (tid < o) red[tid] += red[tid + o];
        __syncthreads();
    }
    float mean = red[0] * (1.0f / INF);
    __syncthreads();

    float a = 0.f;
#pragma unroll
    for (int j = 0; j < 16; ++j) {
        float d = vals[j] - mean;
        a += fabsf(fminf(fmaxf(d, -1.f), 1.f));
        uint32_t word = __ballot_sync(0xffffffffu, d > 0.f);
        if (lane == 0) g_wb[(size_t)row * KW + warp * 16 + j] = word;
    }
    red[tid] = a;
    __syncthreads();
    for (int o = 128; o > 0; o >>= 1) {
        if (tid < o) red[tid] += red[tid + o];
        __syncthreads();
    }
    if (tid == 0) g_wscale[row] = red[0] * (1.0f / INF);
}

// ---------------------------------------------------------------------------
// Kernel 4: XNOR-popcount GEMM, 512 threads.
//   CTA tile 128(M) x 256(N), 16 warps (warp 32Mx64N), thread 8x8.
//   K chunks of 32 words, 3-stage cp.async ring, pitch 144B.
// ---------------------------------------------------------------------------
#define KC 32
#define PITCH 144
#define TROWS (128 + 256)                  // A rows + B rows per stage
#define STG_BYTES (TROWS * PITCH)          // 55296
#define NST 3
#define NCHUNK (KW / KC)                   // 4
#define GEMM_SMEM (NST * STG_BYTES)        // 165888

__global__ __launch_bounds__(512, 1) void gemm_kernel(const float* __restrict__ bias,
                                                      float* __restrict__ out) {
    extern __shared__ char smem_raw[];
    const uint32_t sbase = smem_u32(smem_raw);

    const int tid = threadIdx.x;
    const int wid = tid >> 5;
    const int lane = tid & 31;
    const int wm = wid >> 2;        // 0..3  (M warp)
    const int wn = wid & 3;         // 0..3  (N warp)
    const int tm = lane >> 3;       // 0..3
    const int tn = lane & 7;        // 0..7
    const int tile_n = blockIdx.x;  // 0..15
    const int tile_m = blockIdx.y;  // 0..63

    // ---- producer mapping: 6 x 16B chunks per thread per stage ----------
    // chunk id = tid + 512*i  ->  row = id>>3 (= r0 + 64*i), col16 = tid&7
    const int r0 = tid >> 3;        // 0..63
    const int col16 = tid & 7;
    // i=0,1 -> A rows r0, r0+64 ; i=2..5 -> B rows r0+64*(i-2)
    const uint32_t* gA = g_xb + ((size_t)tile_m * 128 + r0) * KW + col16 * 4;
    const uint32_t* gB = g_wb + ((size_t)tile_n * 256 + r0) * KW + col16 * 4;
    const uint32_t sA = (uint32_t)r0 * PITCH + (uint32_t)col16 * 16;
    const uint32_t sB = (uint32_t)(128 + r0) * PITCH + (uint32_t)col16 * 16;

#define FILL_STAGE(stg_off, kc_words)                                        \
    do {                                                                     \
        uint32_t _b = sbase + (stg_off);                                     \
        const uint32_t* _ga = gA + (kc_words);                               \
        const uint32_t* _gb = gB + (kc_words);                               \
        cp_async16(_b + sA, _ga);                                            \
        cp_async16(_b + sA + 64u * PITCH, _ga + (size_t)64 * KW);            \
        cp_async16(_b + sB, _gb);                                            \
        cp_async16(_b + sB + 64u * PITCH, _gb + (size_t)64 * KW);            \
        cp_async16(_b + sB + 128u * PITCH, _gb + (size_t)128 * KW);          \
        cp_async16(_b + sB + 192u * PITCH, _gb + (size_t)192 * KW);          \
    } while (0)

    // prologue: fill stages 0, 1
#pragma unroll
    for (int s = 0; s < NST - 1; ++s) {
        FILL_STAGE(s * STG_BYTES, s * KC);
        cp_commit();
    }

    int acc[8][8];
#pragma unroll
    for (int i = 0; i < 8; ++i)
#pragma unroll
        for (int j = 0; j < 8; ++j) acc[i][j] = 0;

    const uint32_t aoff = (uint32_t)(wm * 32 + tm) * PITCH;
    const uint32_t boff = (uint32_t)(128 + wn * 64 + tn) * PITCH;

    for (int kc = 0; kc < NCHUNK; ++kc) {
        cp_wait<NST - 2>();
        __syncthreads();

        int ps = kc + NST - 1;
        if (ps < NCHUNK) FILL_STAGE((ps % NST) * STG_BYTES, ps * KC);
        cp_commit();

        const uint32_t stg = sbase + (kc % NST) * STG_BYTES;
#pragma unroll 1
        for (int k4 = 0; k4 < KC / 4; ++k4) {
            const uint32_t kb = (uint32_t)k4 * 16;
            uint4 a[8];
#pragma unroll
            for (int i = 0; i < 8; ++i)
                a[i] = lds128(stg + aoff + (uint32_t)(i * 4) * PITCH + kb);
#pragma unroll
            for (int j = 0; j < 8; ++j) {
                uint4 b = lds128(stg + boff + (uint32_t)(j * 8) * PITCH + kb);
#pragma unroll
                for (int i = 0; i < 8; ++i) {
                    int p0 = __popc(a[i].x ^ b.x) + __popc(a[i].y ^ b.y);
                    int p1 = __popc(a[i].z ^ b.z) + __popc(a[i].w ^ b.w);
                    acc[i][j] += p0 + p1;
                }
            }
        }
    }

    // ---- epilogue -------------------------------------------------------
    const int mb = tile_m * 128 + wm * 32 + tm;
    const int nb = tile_n * 256 + wn * 64 + tn;
#pragma unroll
    for (int j = 0; j < 8; ++j) {
        int n = nb + 8 * j;
        float bv = bias[n];
        float sv = g_wscale[n];
#pragma unroll
        for (int i = 0; i < 8; ++i) {
            int m = mb + 4 * i;
            float v = (float)(INF - 2 * acc[i][j]);
            out[(size_t)m * OUTF + n] = fmaxf((v + bv) * sv, 0.f);
        }
    }
}

// ---------------------------------------------------------------------------
// Launcher
// ---------------------------------------------------------------------------
extern "C" void kernel_launch(void* const* d_in, const int* in_sizes, int n_in,
                              void* d_out, int out_size) {
    (void)in_sizes; (void)n_in; (void)out_size;
    const float* x     = (const float*)d_in[0];
    const float* gamma = (const float*)d_in[1];
    const float* beta  = (const float*)d_in[2];
    const float* w     = (const float*)d_in[3];
    const float* bias  = (const float*)d_in[4];
    float* out = (float*)d_out;

    stats_partial_kernel<<<dim3(16, 32), 256>>>(x);
    stats_finalize_kernel<<<16, 256>>>(gamma, beta);
    binx_pack<<<dim3(BATCH, 4), 256>>>(x);
    binw_pack<<<OUTF, 256>>>(w);

    cudaFuncSetAttribute(gemm_kernel, cudaFuncAttributeMaxDynamicSharedMemorySize, GEMM_SMEM);
    gemm_kernel<<<dim3(OUTF / 256, BATCH / 128), 512, GEMM_SMEM>>>(bias, out);
}

// round 5
// speedup vs baseline: 2.1209x; 1.0474x over previous
#include <cuda_runtime.h>
#include <cstdint>

// ---------------------------------------------------------------------------
// Problem constants
// ---------------------------------------------------------------------------
#define BATCH 8192
#define INF   4096
#define OUTF  4096
#define EPS   1e-4f
#define KW    (INF / 32)          // 128 words per row

// ---------------------------------------------------------------------------
// Scratch (device globals — no allocation allowed)
// ---------------------------------------------------------------------------
__device__ uint32_t g_xb[(size_t)BATCH * KW];   // 4 MB packed sign bits
__device__ uint32_t g_wb[(size_t)OUTF * KW];    // 2 MB
__device__ float g_wscale[OUTF];
__device__ float g_thr[INF];
__device__ uint32_t g_flip[INF];
__device__ float g_psum[32 * INF];
__device__ float g_psq[32 * INF];

// ---------------------------------------------------------------------------
// helpers
// ---------------------------------------------------------------------------
__device__ __forceinline__ uint32_t smem_u32(const void* p) {
    uint32_t a;
    asm("{ .reg .u64 t; cvta.to.shared.u64 t, %1; cvt.u32.u64 %0, t; }"
        : "=r"(a) : "l"(p));
    return a;
}
__device__ __forceinline__ void cp_async16(uint32_t dst, const void* src) {
    asm volatile("cp.async.cg.shared.global [%0], [%1], 16;"
                 :: "r"(dst), "l"(src) : "memory");
}
__device__ __forceinline__ void cp_commit() {
    asm volatile("cp.async.commit_group;" ::: "memory");
}
template <int N>
__device__ __forceinline__ void cp_wait() {
    asm volatile("cp.async.wait_group %0;" :: "n"(N) : "memory");
}
__device__ __forceinline__ uint4 lds128(uint32_t addr) {
    uint4 v;
    asm volatile("ld.shared.v4.b32 {%0, %1, %2, %3}, [%4];"
                 : "=r"(v.x), "=r"(v.y), "=r"(v.z), "=r"(v.w) : "r"(addr));
    return v;
}
// acc += p * one  (one == 1 at runtime, opaque to ptxas -> IMAD on fma pipe)
__device__ __forceinline__ void mad_acc(int& acc, int p, int one) {
    asm("mad.lo.s32 %0, %1, %2, %0;" : "+r"(acc) : "r"(p), "r"(one));
}

// ---------------------------------------------------------------------------
// Kernel 1a: column partial sums (deterministic two-pass stats)
// ---------------------------------------------------------------------------
__global__ __launch_bounds__(256) void stats_partial_kernel(const float* __restrict__ x) {
    int c = blockIdx.x * 256 + threadIdx.x;
    int rc = blockIdx.y;
    float s = 0.f, q = 0.f;
    int r0 = rc * (BATCH / 32);
    for (int r = r0; r < r0 + (BATCH / 32); ++r) {
        float v = x[(size_t)r * INF + c];
        s += v;
        q += v * v;
    }
    g_psum[rc * INF + c] = s;
    g_psq[rc * INF + c] = q;
}

// Kernel 1b: finalize -> per-column threshold + flip
__global__ __launch_bounds__(256) void stats_finalize_kernel(const float* __restrict__ gamma,
                                                             const float* __restrict__ beta) {
    int c = blockIdx.x * 256 + threadIdx.x;
    float s = 0.f, q = 0.f;
    for (int rc = 0; rc < 32; ++rc) {
        s += g_psum[rc * INF + c];
        q += g_psq[rc * INF + c];
    }
    float mu = s * (1.0f / BATCH);
    float var = q * (1.0f / BATCH) - mu * mu;
    float rstd = rsqrtf(var + EPS);
    float sc = gamma[c] * rstd;
    float t;
    uint32_t fl;
    if (sc > 0.f) { t = mu - beta[c] / sc; fl = 0u; }
    else if (sc < 0.f) { t = mu - beta[c] / sc; fl = 1u; }
    else {
        t = (beta[c] > 0.f) ? __int_as_float(0xff800000)   // -inf -> always 1
                            : __int_as_float(0x7f800000);  // +inf -> always 0
        fl = 0u;
    }
    g_thr[c] = t;
    g_flip[c] = fl;
}

// ---------------------------------------------------------------------------
// Kernel 2: pack activation sign bits via ballot.
// ---------------------------------------------------------------------------
__global__ __launch_bounds__(256) void binx_pack(const float* __restrict__ x) {
    int row = blockIdx.x;
    int warp = threadIdx.x >> 5;
    int lane = threadIdx.x & 31;
    int c0 = (blockIdx.y * 8 + warp) * 128;
    const float* xr = x + (size_t)row * INF + c0 + lane;
    uint32_t* ow = g_xb + (size_t)row * KW + (blockIdx.y * 8 + warp) * 4;
#pragma unroll
    for (int j = 0; j < 4; ++j) {
        int c = c0 + lane + 32 * j;
        float v = xr[32 * j];
        uint32_t bit = ((v > g_thr[c]) ? 1u : 0u) ^ g_flip[c];
        uint32_t word = __ballot_sync(0xffffffffu, bit);
        if (lane == 0) ow[j] = word;
    }
}

// ---------------------------------------------------------------------------
// Kernel 3: pack weight sign bits (row-centered) + per-row L1 scale.
// ---------------------------------------------------------------------------
__global__ __launch_bounds__(256) void binw_pack(const float* __restrict__ w) {
    __shared__ float red[256];
    int row = blockIdx.x;
    int tid = threadIdx.x;
    int warp = tid >> 5;
    int lane = tid & 31;
    const float* wr = w + (size_t)row * INF;

    float vals[16];
    float s = 0.f;
#pragma unroll
    for (int j = 0; j < 16; ++j) {
        vals[j] = wr[warp * 512 + lane + 32 * j];
        s += vals[j];
    }
    red[tid] = s;
    __syncthreads();
    for (int o = 128; o > 0; o >>= 1) {
        if (tid < o) red[tid] += red[tid + o];
        __syncthreads();
    }
    float mean = red[0] * (1.0f / INF);
    __syncthreads();

    float a = 0.f;
#pragma unroll
    for (int j = 0; j < 16; ++j) {
        float d = vals[j] - mean;
        a += fabsf(fminf(fmaxf(d, -1.f), 1.f));
        uint32_t word = __ballot_sync(0xffffffffu, d > 0.f);
        if (lane == 0) g_wb[(size_t)row * KW + warp * 16 + j] = word;
    }
    red[tid] = a;
    __syncthreads();
    for (int o = 128; o > 0; o >>= 1) {
        if (tid < o) red[tid] += red[tid + o];
        __syncthreads();
    }
    if (tid == 0) g_wscale[row] = red[0] * (1.0f / INF);
}

// ---------------------------------------------------------------------------
// Kernel 4: XNOR-popcount GEMM, 512 threads.
//   CTA tile 128(M) x 256(N), 16 warps (warp 32Mx64N), thread 8x8.
//   K chunks of 32 words, 3-stage cp.async ring, pitch 144B.
//   Accumulation via IMAD (fma pipe) so alu pipe only carries XOR+POPC.
// ---------------------------------------------------------------------------
#define KC 32
#define PITCH 144
#define TROWS (128 + 256)                  // A rows + B rows per stage
#define STG_BYTES (TROWS * PITCH)          // 55296
#define NST 3
#define NCHUNK (KW / KC)                   // 4
#define GEMM_SMEM (NST * STG_BYTES)        // 165888

__global__ __launch_bounds__(512, 1) void gemm_kernel(const float* __restrict__ bias,
                                                      float* __restrict__ out) {
    extern __shared__ char smem_raw[];
    const uint32_t sbase = smem_u32(smem_raw);

    const int tid = threadIdx.x;
    const int wid = tid >> 5;
    const int lane = tid & 31;
    const int wm = wid >> 2;        // 0..3  (M warp)
    const int wn = wid & 3;         // 0..3  (N warp)
    const int tm = lane >> 3;       // 0..3
    const int tn = lane & 7;        // 0..7
    const int tile_n = blockIdx.x;  // 0..15
    const int tile_m = blockIdx.y;  // 0..63
    const int one = (int)(blockDim.x >> 9);   // == 1, opaque to ptxas

    // ---- producer mapping: 6 x 16B chunks per thread per stage ----------
    const int r0 = tid >> 3;        // 0..63
    const int col16 = tid & 7;
    const uint32_t* gA = g_xb + ((size_t)tile_m * 128 + r0) * KW + col16 * 4;
    const uint32_t* gB = g_wb + ((size_t)tile_n * 256 + r0) * KW + col16 * 4;
    const uint32_t sA = (uint32_t)r0 * PITCH + (uint32_t)col16 * 16;
    const uint32_t sB = (uint32_t)(128 + r0) * PITCH + (uint32_t)col16 * 16;

#define FILL_STAGE(stg_off, kc_words)                                        \
    do {                                                                     \
        uint32_t _b = sbase + (stg_off);                                     \
        const uint32_t* _ga = gA + (kc_words);                               \
        const uint32_t* _gb = gB + (kc_words);                               \
        cp_async16(_b + sA, _ga);                                            \
        cp_async16(_b + sA + 64u * PITCH, _ga + (size_t)64 * KW);            \
        cp_async16(_b + sB, _gb);                                            \
        cp_async16(_b + sB + 64u * PITCH, _gb + (size_t)64 * KW);            \
        cp_async16(_b + sB + 128u * PITCH, _gb + (size_t)128 * KW);          \
        cp_async16(_b + sB + 192u * PITCH, _gb + (size_t)192 * KW);          \
    } while (0)

    // prologue: fill stages 0, 1
#pragma unroll
    for (int s = 0; s < NST - 1; ++s) {
        FILL_STAGE(s * STG_BYTES, s * KC);
        cp_commit();
    }

    int acc[8][8];
#pragma unroll
    for (int i = 0; i < 8; ++i)
#pragma unroll
        for (int j = 0; j < 8; ++j) acc[i][j] = 0;

    const uint32_t aoff = (uint32_t)(wm * 32 + tm) * PITCH;
    const uint32_t boff = (uint32_t)(128 + wn * 64 + tn) * PITCH;

    for (int kc = 0; kc < NCHUNK; ++kc) {
        cp_wait<NST - 2>();
        __syncthreads();

        int ps = kc + NST - 1;
        if (ps < NCHUNK) FILL_STAGE((ps % NST) * STG_BYTES, ps * KC);
        cp_commit();

        const uint32_t stg = sbase + (kc % NST) * STG_BYTES;
#pragma unroll 1
        for (int k4 = 0; k4 < KC / 4; ++k4) {
            const uint32_t kb = (uint32_t)k4 * 16;
            uint4 a[8];
#pragma unroll
            for (int i = 0; i < 8; ++i)
                a[i] = lds128(stg + aoff + (uint32_t)(i * 4) * PITCH + kb);
#pragma unroll
            for (int j = 0; j < 8; ++j) {
                uint4 b = lds128(stg + boff + (uint32_t)(j * 8) * PITCH + kb);
#pragma unroll
                for (int i = 0; i < 8; ++i) {
                    mad_acc(acc[i][j], __popc(a[i].x ^ b.x), one);
                    mad_acc(acc[i][j], __popc(a[i].y ^ b.y), one);
                    mad_acc(acc[i][j], __popc(a[i].z ^ b.z), one);
                    mad_acc(acc[i][j], __popc(a[i].w ^ b.w), one);
                }
            }
        }
    }

    // ---- epilogue -------------------------------------------------------
    const int mb = tile_m * 128 + wm * 32 + tm;
    const int nb = tile_n * 256 + wn * 64 + tn;
#pragma unroll
    for (int j = 0; j < 8; ++j) {
        int n = nb + 8 * j;
        float bv = bias[n];
        float sv = g_wscale[n];
#pragma unroll
        for (int i = 0; i < 8; ++i) {
            int m = mb + 4 * i;
            float v = (float)(INF - 2 * acc[i][j]);
            out[(size_t)m * OUTF + n] = fmaxf((v + bv) * sv, 0.f);
        }
    }
}

// ---------------------------------------------------------------------------
// Launcher
// ---------------------------------------------------------------------------
extern "C" void kernel_launch(void* const* d_in, const int* in_sizes, int n_in,
                              void* d_out, int out_size) {
    (void)in_sizes; (void)n_in; (void)out_size;
    const float* x     = (const float*)d_in[0];
    const float* gamma = (const float*)d_in[1];
    const float* beta  = (const float*)d_in[2];
    const float* w     = (const float*)d_in[3];
    const float* bias  = (const float*)d_in[4];
    float* out = (float*)d_out;

    stats_partial_kernel<<<dim3(16, 32), 256>>>(x);
    stats_finalize_kernel<<<16, 256>>>(gamma, beta);
    binx_pack<<<dim3(BATCH, 4), 256>>>(x);
    binw_pack<<<OUTF, 256>>>(w);

    cudaFuncSetAttribute(gemm_kernel, cudaFuncAttributeMaxDynamicSharedMemorySize, GEMM_SMEM);
    gemm_kernel<<<dim3(OUTF / 256, BATCH / 128), 512, GEMM_SMEM>>>(bias, out);
}